// round 12
// baseline (speedup 1.0000x reference)
#include <cuda_runtime.h>
#include <cuda_bf16.h>
#include <cstdint>

// Embedding gather with id-locality pre-sort:
//   out[row, :] = weight[ids[row], :],  row = 3072 B.
// K1 (1 CTA, 1024 thr): bucket-sort the 8192 (id, token) pairs by id>>6
//   (512 buckets). Makes the main kernel's weight reads sweep the table
//   in near-ascending address order -> DRAM row-buffer locality.
// K2 (1024 CTAs, 32 thr): R3-proven shape — 8 rows/CTA, per-row mbarrier
//   TMA G->S gather from weight[sorted_id], TMA S->G store to
//   out[sorted_tok] (3KB contiguous per row; write scatter is cheap).

static constexpr int DIM       = 768;
static constexpr int ROW_BYTES = DIM * 4;                  // 3072
static constexpr int N_TOK     = 8192;
static constexpr int ROWS      = 8;
static constexpr int BUF_BYTES = ROWS * ROW_BYTES;         // 24576
static constexpr int NBUCKET   = 512;                      // id>>6, 64 rows/bucket

__device__ int g_sorted_id [N_TOK];
__device__ int g_sorted_tok[N_TOK];

// ---------------- K1: bucket sort ----------------
__global__ __launch_bounds__(1024) void sort_kernel(const int* __restrict__ ids)
{
    __shared__ int sids[N_TOK];        // 32KB
    __shared__ int hist[NBUCKET];
    __shared__ int offs[NBUCKET];
    __shared__ int wtot[16];

    const int t = threadIdx.x;

    if (t < NBUCKET) hist[t] = 0;
    __syncthreads();

    // load ids + histogram
    for (int i = t; i < N_TOK; i += 1024) {
        int id = ids[i];
        sids[i] = id;
        atomicAdd(&hist[id >> 6], 1);
    }
    __syncthreads();

    // exclusive scan of 512 bins (warp scan + 16-partial scan)
    int excl = 0;
    if (t < NBUCKET) {
        const int lane = t & 31, w = t >> 5;
        int v = hist[t];
        int inc = v;
#pragma unroll
        for (int d = 1; d < 32; d <<= 1) {
            int x = __shfl_up_sync(0xffffffffu, inc, d);
            if (lane >= d) inc += x;
        }
        excl = inc - v;
        if (lane == 31) wtot[w] = inc;
    }
    __syncthreads();
    if (t == 0) {
        int run = 0;
#pragma unroll
        for (int w = 0; w < 16; w++) { int x = wtot[w]; wtot[w] = run; run += x; }
    }
    __syncthreads();
    if (t < NBUCKET) offs[t] = excl + wtot[t >> 5];
    __syncthreads();

    // scatter (order within bucket arbitrary; final out is order-invariant)
    for (int i = t; i < N_TOK; i += 1024) {
        int id  = sids[i];
        int pos = atomicAdd(&offs[id >> 6], 1);
        g_sorted_id [pos] = id;
        g_sorted_tok[pos] = i;
    }
}

// ---------------- K2: sorted TMA gather (R3 shape) ----------------
__global__ __launch_bounds__(32) void gather_kernel(
    const float* __restrict__ weight,
    float* __restrict__ out)
{
    __shared__ __align__(128) unsigned char buf[BUF_BYTES];
    __shared__ __align__(8)  unsigned long long mbar[ROWS];

    const int base = blockIdx.x * ROWS;
    if (threadIdx.x != 0) return;

    uint32_t sb  = (uint32_t)__cvta_generic_to_shared(buf);
    uint32_t mb0 = (uint32_t)__cvta_generic_to_shared(mbar);

#pragma unroll
    for (int s = 0; s < ROWS; s++)
        asm volatile("mbarrier.init.shared.b64 [%0], 1;"
                     :: "r"(mb0 + s * 8) : "memory");
    asm volatile("fence.proxy.async.shared::cta;" ::: "memory");

    int id[ROWS], tok[ROWS];
#pragma unroll
    for (int s = 0; s < ROWS; s++) {
        id [s] = g_sorted_id [base + s];
        tok[s] = g_sorted_tok[base + s];
    }

    // G->S gathers in ascending-id order (DRAM-row locality).
#pragma unroll
    for (int s = 0; s < ROWS; s++) {
        uint32_t mb = mb0 + s * 8;
        const void* src = (const char*)weight + (size_t)id[s] * ROW_BYTES;
        asm volatile("mbarrier.arrive.expect_tx.shared.b64 _, [%0], %1;"
                     :: "r"(mb), "r"(ROW_BYTES) : "memory");
        asm volatile(
            "cp.async.bulk.shared::cta.global.mbarrier::complete_tx::bytes "
            "[%0], [%1], %2, [%3];"
            :: "r"(sb + s * ROW_BYTES), "l"(src), "r"(ROW_BYTES), "r"(mb)
            : "memory");
    }

    // Drain rows as they land; stores scattered by token (3KB contiguous each).
#pragma unroll
    for (int s = 0; s < ROWS; s++) {
        uint32_t mb = mb0 + s * 8;
        uint32_t done = 0;
        while (!done) {
            asm volatile(
                "{\n\t.reg .pred p;\n\t"
                "mbarrier.try_wait.parity.acquire.cta.shared::cta.b64 p, [%1], 0, 0x989680;\n\t"
                "selp.b32 %0, 1, 0, p;\n\t}"
                : "=r"(done) : "r"(mb) : "memory");
        }
        void* dstg = (char*)out + (size_t)tok[s] * ROW_BYTES;
        asm volatile(
            "cp.async.bulk.global.shared::cta.bulk_group [%0], [%1], %2;"
            :: "l"(dstg), "r"(sb + s * ROW_BYTES), "r"(ROW_BYTES) : "memory");
    }
    asm volatile("cp.async.bulk.commit_group;" ::: "memory");
    asm volatile("cp.async.bulk.wait_group 0;" ::: "memory");
}

extern "C" void kernel_launch(void* const* d_in, const int* in_sizes, int n_in,
                              void* d_out, int out_size)
{
    const int*   ids    = (const int*)d_in[0];     // [8192] int32
    const float* weight = (const float*)d_in[1];   // [32000, 768] f32
    float*       out    = (float*)d_out;           // [8192, 768] f32

    sort_kernel<<<1, 1024>>>(ids);
    gather_kernel<<<N_TOK / ROWS, 32>>>(weight, out);
}

// round 13
// speedup vs baseline: 1.9791x; 1.9791x over previous
#include <cuda_runtime.h>
#include <cuda_bf16.h>
#include <cstdint>

// Embedding gather, R3 pipeline at 16 rows/CTA:
//   out[row, :] = weight[ids[row], :],  row = 3072 B.
// 512 CTAs x 32 threads. Per-row mbarrier + per-row S2G store-as-it-lands
// (the combination R4 got wrong: R4 used ONE wait for all rows).
// Lanes 0-15 load ids coalesced; lane 0 issues all TMA ops.
// Cache hints: weight reads evict_last, out stores evict_first (free).

static constexpr int DIM       = 768;
static constexpr int ROW_BYTES = DIM * 4;                 // 3072
static constexpr int ROWS      = 16;
static constexpr int BUF_BYTES = ROWS * ROW_BYTES;        // 49152

__global__ __launch_bounds__(32) void emb_kernel(
    const int* __restrict__ ids,
    const float* __restrict__ weight,
    float* __restrict__ out)
{
    __shared__ __align__(128) unsigned char buf[BUF_BYTES];
    __shared__ __align__(8)  unsigned long long mbar[ROWS];
    __shared__ int sid[ROWS];

    const int base = blockIdx.x * ROWS;
    const int t    = threadIdx.x;

    uint32_t sb  = (uint32_t)__cvta_generic_to_shared(buf);
    uint32_t mb0 = (uint32_t)__cvta_generic_to_shared(mbar);

    // Parallel prologue: lanes 0-15 init one barrier + load one id each.
    if (t < ROWS) {
        asm volatile("mbarrier.init.shared.b64 [%0], 1;"
                     :: "r"(mb0 + t * 8) : "memory");
        sid[t] = __ldg(&ids[base + t]);
    }
    __syncwarp();
    if (t == 0)
        asm volatile("fence.proxy.async.shared::cta;" ::: "memory");
    __syncwarp();

    if (t != 0) return;   // lane 0 runs the TMA pipeline

    uint64_t pol_keep, pol_stream;
    asm volatile("createpolicy.fractional.L2::evict_last.b64 %0, 1.0;"
                 : "=l"(pol_keep));
    asm volatile("createpolicy.fractional.L2::evict_first.b64 %0, 1.0;"
                 : "=l"(pol_stream));

    // Issue all 16 G->S gathers (independent, deep in-flight).
#pragma unroll
    for (int s = 0; s < ROWS; s++) {
        uint32_t mb = mb0 + s * 8;
        const void* src = (const char*)weight + (size_t)sid[s] * ROW_BYTES;
        asm volatile("mbarrier.arrive.expect_tx.shared.b64 _, [%0], %1;"
                     :: "r"(mb), "r"(ROW_BYTES) : "memory");
        asm volatile(
            "cp.async.bulk.shared::cta.global.mbarrier::complete_tx::bytes"
            ".L2::cache_hint [%0], [%1], %2, [%3], %4;"
            :: "r"(sb + s * ROW_BYTES), "l"(src), "r"(ROW_BYTES), "r"(mb),
               "l"(pol_keep)
            : "memory");
    }

    // Drain rows AS THEY LAND (per-row wait -> per-row S2G).
#pragma unroll
    for (int s = 0; s < ROWS; s++) {
        uint32_t mb = mb0 + s * 8;
        uint32_t done = 0;
        while (!done) {
            asm volatile(
                "{\n\t.reg .pred p;\n\t"
                "mbarrier.try_wait.parity.acquire.cta.shared::cta.b64 p, [%1], 0, 0x989680;\n\t"
                "selp.b32 %0, 1, 0, p;\n\t}"
                : "=r"(done) : "r"(mb) : "memory");
        }
        void* dstg = (char*)out + (size_t)(base + s) * ROW_BYTES;
        asm volatile(
            "cp.async.bulk.global.shared::cta.bulk_group.L2::cache_hint "
            "[%0], [%1], %2, %3;"
            :: "l"(dstg), "r"(sb + s * ROW_BYTES), "r"(ROW_BYTES),
               "l"(pol_stream)
            : "memory");
    }
    asm volatile("cp.async.bulk.commit_group;" ::: "memory");
    asm volatile("cp.async.bulk.wait_group 0;" ::: "memory");
}

extern "C" void kernel_launch(void* const* d_in, const int* in_sizes, int n_in,
                              void* d_out, int out_size)
{
    const int*   ids    = (const int*)d_in[0];     // [8192] int32
    const float* weight = (const float*)d_in[1];   // [32000, 768] f32
    float*       out    = (float*)d_out;           // [8192, 768] f32

    const int n_rows = in_sizes[0];                // 8192
    const int n_ctas = n_rows / ROWS;              // 512
    emb_kernel<<<n_ctas, 32>>>(ids, weight, out);
}

// round 17
// speedup vs baseline: 2.0400x; 1.0308x over previous
#include <cuda_runtime.h>
#include <cuda_bf16.h>
#include <cstdint>

// Embedding gather: TMA bulk G->S + coalesced STG drain, 2-row drain granularity.
//   out[row, :] = weight[ids[row], :], row = 3072 B.
// Proven-optimal shape: 1024 CTAs x 192 threads, 8 rows/CTA.
// 4 mbarriers x 2 rows each: drain starts as soon as the first 2 rows land
// (earlier STG/TMA overlap than R9's 4-row halves, fewer barriers than R3's 8).
// Lanes 0-7 load ids coalesced into shared (parallel prologue).

static constexpr int DIM        = 768;
static constexpr int VEC        = DIM / 4;                  // 192 float4/row
static constexpr int ROW_BYTES  = DIM * 4;                  // 3072
static constexpr int ROWS       = 8;
static constexpr int GROUPS     = 4;                        // barriers
static constexpr int G_ROWS     = ROWS / GROUPS;            // 2 rows per barrier
static constexpr int G_BYTES    = G_ROWS * ROW_BYTES;       // 6144
static constexpr int BUF_BYTES  = ROWS * ROW_BYTES;         // 24576
static constexpr int THREADS    = VEC;                      // 192

__global__ __launch_bounds__(THREADS) void emb_kernel(
    const int* __restrict__ ids,
    const float* __restrict__ weight,
    float* __restrict__ out)
{
    __shared__ __align__(128) unsigned char buf[BUF_BYTES];
    __shared__ __align__(8)  unsigned long long mbar[GROUPS];
    __shared__ int sid[ROWS];

    const int base = blockIdx.x * ROWS;
    const int t    = threadIdx.x;

    uint32_t sb  = (uint32_t)__cvta_generic_to_shared(buf);
    uint32_t mb0 = (uint32_t)__cvta_generic_to_shared(mbar);

    // Parallel prologue: lanes 0-3 init barriers, lanes 0-7 load ids.
    if (t < GROUPS)
        asm volatile("mbarrier.init.shared.b64 [%0], 1;"
                     :: "r"(mb0 + t * 8) : "memory");
    if (t < ROWS)
        sid[t] = __ldg(&ids[base + t]);
    __syncthreads();   // init + ids visible; also orders init before TMA

    if (t == 0) {
        asm volatile("fence.proxy.async.shared::cta;" ::: "memory");
        // Issue 4 groups x 2 rows of G->S bulk gathers.
#pragma unroll
        for (int g = 0; g < GROUPS; g++) {
            uint32_t mb = mb0 + g * 8;
            asm volatile("mbarrier.arrive.expect_tx.shared.b64 _, [%0], %1;"
                         :: "r"(mb), "r"(G_BYTES) : "memory");
#pragma unroll
            for (int k = 0; k < G_ROWS; k++) {
                int s = g * G_ROWS + k;
                const void* src = (const char*)weight + (size_t)sid[s] * ROW_BYTES;
                asm volatile(
                    "cp.async.bulk.shared::cta.global.mbarrier::complete_tx::bytes "
                    "[%0], [%1], %2, [%3];"
                    :: "r"(sb + s * ROW_BYTES), "l"(src), "r"(ROW_BYTES), "r"(mb)
                    : "memory");
            }
        }
    }

    const float4* sbuf = (const float4*)buf;
    float4*       o4   = (float4*)out + (size_t)base * VEC;

    // Drain each 2-row group as it lands: all 192 threads, 2 float4 each.
#pragma unroll
    for (int g = 0; g < GROUPS; g++) {
        uint32_t mb = mb0 + g * 8;
        uint32_t done = 0;
        while (!done) {
            asm volatile(
                "{\n\t.reg .pred p;\n\t"
                "mbarrier.try_wait.parity.acquire.cta.shared::cta.b64 p, [%1], 0, 0x989680;\n\t"
                "selp.b32 %0, 1, 0, p;\n\t}"
                : "=r"(done) : "r"(mb) : "memory");
        }
#pragma unroll
        for (int k = 0; k < G_ROWS; k++) {
            int i = (g * G_ROWS + k) * VEC + t;   // coalesced
            o4[i] = sbuf[i];
        }
    }
}

extern "C" void kernel_launch(void* const* d_in, const int* in_sizes, int n_in,
                              void* d_out, int out_size)
{
    const int*   ids    = (const int*)d_in[0];     // [8192] int32
    const float* weight = (const float*)d_in[1];   // [32000, 768] f32
    float*       out    = (float*)d_out;           // [8192, 768] f32

    const int n_rows = in_sizes[0];                // 8192
    const int n_ctas = n_rows / ROWS;              // 1024
    emb_kernel<<<n_ctas, THREADS>>>(ids, weight, out);
}